// round 16
// baseline (speedup 1.0000x reference)
#include <cuda_runtime.h>
#include <cuda_bf16.h>
#include <cuda_fp16.h>
#include <math.h>
#include <stdint.h>

#define TT 8192   // sequence length T
#define EE 4096   // embedding E

// ============================ scratch (576MB + vecs, reused) =================
static constexpr size_t MB = 1ull << 20;
// Pool A @0 (128MB): tokT h/l -> Gh/Gl + Uh/Ul -> WpTl
static constexpr size_t OFF_TOKTH = 0,      OFF_TOKTL = 64*MB;
static constexpr size_t OFF_GH    = 0,      OFF_GL    = 32*MB;
static constexpr size_t OFF_UH    = 64*MB,  OFF_UL    = 96*MB;
static constexpr size_t OFF_WPTL  = 0;
// Pool B @128 (64MB): G fp32 -> P1 h/l -> Wv h/l
static constexpr size_t OFF_GF    = 128*MB;
static constexpr size_t OFF_P1H   = 128*MB, OFF_P1L   = 160*MB;
static constexpr size_t OFF_WVH   = 128*MB, OFF_WVL   = 160*MB;
// Pool C @192 (64MB): WqT h/l -> WkT h/l -> att h/l
static constexpr size_t OFF_WQTH  = 192*MB, OFF_WQTL  = 224*MB;
static constexpr size_t OFF_WKTH  = 192*MB, OFF_WKTL  = 224*MB;
static constexpr size_t OFF_ATH   = 192*MB, OFF_ATL   = 224*MB;
// Pool D @256 (64MB): S fp32
static constexpr size_t OFF_S     = 256*MB;
// Pool E @320 (128MB): tok h/l -> WpTh
static constexpr size_t OFF_TOKH  = 320*MB, OFF_TOKL  = 384*MB;
static constexpr size_t OFF_WPTH  = 320*MB;
// Pool F @448 (128MB): o h/l
static constexpr size_t OFF_OH    = 448*MB, OFF_OL    = 512*MB;
// vectors
static constexpr size_t OFF_VS    = 576*MB;            // s [E]
static constexpr size_t OFF_VU    = 576*MB + 16384;    // u [E]
static constexpr size_t OFF_VW    = 576*MB + 32768;    // w [E]
static constexpr size_t OFF_VR    = 576*MB + 49152;    // r [E]
static constexpr size_t TOTAL_SCRATCH = 576*MB + 65536;
__device__ __align__(1024) unsigned char g_scratch[TOTAL_SCRATCH];

// ============================ PTX helpers ===================================
__device__ __forceinline__ uint32_t smem_u32(const void* p) {
    uint32_t a;
    asm("{ .reg .u64 t; cvta.to.shared.u64 t, %1; cvt.u32.u64 %0, t; }" : "=r"(a) : "l"(p));
    return a;
}
__device__ __forceinline__ void cp16(uint32_t s, const void* g) {
    asm volatile("cp.async.cg.shared.global [%0], [%1], 16;" :: "r"(s), "l"(g));
}
__device__ __forceinline__ void ldm_x4(uint32_t* r, uint32_t addr) {
    asm volatile("ldmatrix.sync.aligned.m8n8.x4.shared.b16 {%0,%1,%2,%3}, [%4];"
                 : "=r"(r[0]), "=r"(r[1]), "=r"(r[2]), "=r"(r[3]) : "r"(addr));
}
// fp16 inputs, fp32 accumulate
__device__ __forceinline__ void mma16816(float* c, const uint32_t* a, const uint32_t* b) {
    asm volatile(
        "mma.sync.aligned.m16n8k16.row.col.f32.f16.f16.f32 "
        "{%0,%1,%2,%3}, {%4,%5,%6,%7}, {%8,%9}, {%0,%1,%2,%3};"
        : "+f"(c[0]), "+f"(c[1]), "+f"(c[2]), "+f"(c[3])
        : "r"(a[0]), "r"(a[1]), "r"(a[2]), "r"(a[3]), "r"(b[0]), "r"(b[1]));
}

// fp16 hi/lo split
__device__ __forceinline__ void split1(float x, unsigned short& h, unsigned short& l) {
    __half hb = __float2half_rn(x);
    float r = x - __half2float(hb);
    __half lb = __float2half_rn(r);
    h = __half_as_ushort(hb);
    l = __half_as_ushort(lb);
}

// ============================ fp16-split GEMM (mma.sync) =====================
// C[M,N] = sum_k A[m,k]*B[n,k]; A,B fp16 hi/lo, K-major. Block 128x128x32,
// 256 threads, warp tile 64x32, 2 CTAs/SM.
// BMODE: 0 none, 1 col bias, 2 row bias.  OUT: 0 fp32, 1 hi/lo split.
// TRI: only bm>=bn blocks.
// NT: 3 = hh+hl+lh (2-stage);  2 = hh+hl (3-stage);  1 = hh (3-stage).
// Per-NT compact stage layout; NT<3 issues prefetch right after the barrier.
constexpr int BK = 32;
constexpr int ARR_BYTES = 128 * 80;

template <int NT> struct GemmCfg {
    static constexpr int N_ARR = (NT == 3) ? 4 : (NT == 2) ? 3 : 2;
    static constexpr int STG   = N_ARR * ARR_BYTES;
    static constexpr int NSTG  = (NT == 3) ? 2 : 3;
    static constexpr int SMEM  = NSTG * STG;
    static constexpr int OAH = 0;
    static constexpr int OAL = ARR_BYTES;                       // NT==3 only
    static constexpr int OBH = (NT == 3) ? 2 * ARR_BYTES : ARR_BYTES;
    static constexpr int OBL = (NT == 3) ? 3 * ARR_BYTES : 2 * ARR_BYTES;
};

template <int BMODE, int OUT, bool TRI, int NT>
__global__ __launch_bounds__(256, 2)
void hm_gemm(const unsigned short* __restrict__ Ah, const unsigned short* __restrict__ Al,
             const unsigned short* __restrict__ Bh, const unsigned short* __restrict__ Bl,
             const float* __restrict__ cbias, const float* __restrict__ rbias,
             float* __restrict__ C,
             unsigned short* __restrict__ Chi, unsigned short* __restrict__ Clo,
             int Ntot, int Ktot)
{
    using CFG = GemmCfg<NT>;
    extern __shared__ __align__(128) char smem[];
    const uint32_t sb = smem_u32(smem);
    const int tid = threadIdx.x, lane = tid & 31, wid = tid >> 5;
    const int bm = blockIdx.y * 128, bn = blockIdx.x * 128;
    if (TRI && bm < bn) return;
    const int wm = (wid >> 2) * 64, wn = (wid & 3) * 32;
    const int nch = Ktot >> 5;

    const int r0 = tid >> 2;
    const int lc = (tid & 3) * 8;

    auto load_stage = [&](int stg, int ch) {
        const uint32_t st = sb + stg * CFG::STG;
        const size_t ko = (size_t)(ch * BK) + lc;
        cp16(st + CFG::OAH + (r0)      * 80 + lc * 2, Ah + (size_t)(bm + r0)      * Ktot + ko);
        cp16(st + CFG::OAH + (r0 + 64) * 80 + lc * 2, Ah + (size_t)(bm + r0 + 64) * Ktot + ko);
        if (NT == 3) {
            cp16(st + CFG::OAL + (r0)      * 80 + lc * 2, Al + (size_t)(bm + r0)      * Ktot + ko);
            cp16(st + CFG::OAL + (r0 + 64) * 80 + lc * 2, Al + (size_t)(bm + r0 + 64) * Ktot + ko);
        }
        cp16(st + CFG::OBH + (r0)      * 80 + lc * 2, Bh + (size_t)(bn + r0)      * Ktot + ko);
        cp16(st + CFG::OBH + (r0 + 64) * 80 + lc * 2, Bh + (size_t)(bn + r0 + 64) * Ktot + ko);
        if (NT >= 2) {
            cp16(st + CFG::OBL + (r0)      * 80 + lc * 2, Bl + (size_t)(bn + r0)      * Ktot + ko);
            cp16(st + CFG::OBL + (r0 + 64) * 80 + lc * 2, Bl + (size_t)(bn + r0 + 64) * Ktot + ko);
        }
        asm volatile("cp.async.commit_group;");
    };

    const int sel = lane >> 3, r8 = lane & 7;
    const uint32_t aoffA = (uint32_t)((wm + (sel & 1) * 8 + r8) * 80 + (sel >> 1) * 16);
    const uint32_t aoffB = (uint32_t)((wn + (sel >> 1) * 8 + r8) * 80 + (sel & 1) * 16);

    float acc[4][4][4];
#pragma unroll
    for (int a = 0; a < 4; a++)
#pragma unroll
        for (int b = 0; b < 4; b++)
#pragma unroll
            for (int c = 0; c < 4; c++) acc[a][b][c] = 0.0f;

    load_stage(0, 0);
    if (nch > 1) load_stage(1, 1);

    for (int i = 0; i < nch; i++) {
        asm volatile("cp.async.wait_group 1;");
        __syncthreads();

        const int stg = (CFG::NSTG == 2) ? (i & 1) : (i % 3);
        const uint32_t st = sb + stg * CFG::STG;

        // 3-stage: prefetch target stage was fully read last iteration -> issue now
        if (CFG::NSTG == 3 && i + 2 < nch) load_stage((i + 2) % 3, i + 2);

        uint32_t af[4][4], bh[4][2], bl[4][2];

#pragma unroll
        for (int k16 = 0; k16 < 2; k16++) {
            const uint32_t ko = k16 * 32;
#pragma unroll
            for (int mt = 0; mt < 4; mt++)
                ldm_x4(af[mt], st + CFG::OAH + aoffA + mt * 1280 + ko);
#pragma unroll
            for (int p = 0; p < 2; p++) {
                uint32_t t[4];
                ldm_x4(t, st + CFG::OBH + aoffB + p * 1280 + ko);
                bh[2 * p][0] = t[0]; bh[2 * p][1] = t[1];
                bh[2 * p + 1][0] = t[2]; bh[2 * p + 1][1] = t[3];
                if (NT >= 2) {
                    ldm_x4(t, st + CFG::OBL + aoffB + p * 1280 + ko);
                    bl[2 * p][0] = t[0]; bl[2 * p][1] = t[1];
                    bl[2 * p + 1][0] = t[2]; bl[2 * p + 1][1] = t[3];
                }
            }
#pragma unroll
            for (int mt = 0; mt < 4; mt++)
#pragma unroll
                for (int nt = 0; nt < 4; nt++)
                    mma16816(acc[mt][nt], af[mt], bh[nt]);
            if (NT >= 2) {
#pragma unroll
                for (int mt = 0; mt < 4; mt++)
#pragma unroll
                    for (int nt = 0; nt < 4; nt++)
                        mma16816(acc[mt][nt], af[mt], bl[nt]);
            }
            if (NT == 3) {
#pragma unroll
                for (int mt = 0; mt < 4; mt++)
                    ldm_x4(af[mt], st + CFG::OAL + aoffA + mt * 1280 + ko);
                if (k16 == 1) __syncthreads();   // 2-stage: stage fully read
#pragma unroll
                for (int mt = 0; mt < 4; mt++)
#pragma unroll
                    for (int nt = 0; nt < 4; nt++)
                        mma16816(acc[mt][nt], af[mt], bh[nt]);
            }
        }
        if (CFG::NSTG == 2 && i + 2 < nch) load_stage(i & 1, i + 2);
    }

    // ---- epilogue ----
    const int g = lane >> 2, tg = lane & 3;
#pragma unroll
    for (int mt = 0; mt < 4; mt++) {
#pragma unroll
        for (int nt = 0; nt < 4; nt++) {
            const int m = bm + wm + mt * 16 + g;
            const int n = bn + wn + nt * 8 + tg * 2;
            float c0 = 0.f, c1 = 0.f, rr0 = 0.f, rr1 = 0.f;
            if (BMODE == 1) { c0 = cbias[n]; c1 = cbias[n + 1]; }
            if (BMODE == 2) { rr0 = rbias[m]; rr1 = rbias[m + 8]; }
            float v00 = acc[mt][nt][0] + c0 + rr0, v01 = acc[mt][nt][1] + c1 + rr0;
            float v10 = acc[mt][nt][2] + c0 + rr1, v11 = acc[mt][nt][3] + c1 + rr1;
            if (OUT == 0) {
                *reinterpret_cast<float2*>(&C[(size_t)m * Ntot + n]) = make_float2(v00, v01);
                *reinterpret_cast<float2*>(&C[(size_t)(m + 8) * Ntot + n]) = make_float2(v10, v11);
            } else {
                ushort2 h0, l0, h1, l1;
                split1(v00, h0.x, l0.x); split1(v01, h0.y, l0.y);
                split1(v10, h1.x, l1.x); split1(v11, h1.y, l1.y);
                *reinterpret_cast<ushort2*>(&Chi[(size_t)m * Ntot + n]) = h0;
                *reinterpret_cast<ushort2*>(&Clo[(size_t)m * Ntot + n]) = l0;
                *reinterpret_cast<ushort2*>(&Chi[(size_t)(m + 8) * Ntot + n]) = h1;
                *reinterpret_cast<ushort2*>(&Clo[(size_t)(m + 8) * Ntot + n]) = l1;
            }
        }
    }
}

// ============================ aux kernels ===================================
__global__ __launch_bounds__(256)
void split_dir(const float4* __restrict__ x, ushort4* __restrict__ hi,
               ushort4* __restrict__ lo, size_t n4)
{
    size_t i = (size_t)blockIdx.x * blockDim.x + threadIdx.x;
    if (i >= n4) return;
    float4 v = x[i];
    ushort4 h, l;
    split1(v.x, h.x, l.x); split1(v.y, h.y, l.y);
    split1(v.z, h.z, l.z); split1(v.w, h.w, l.w);
    hi[i] = h; lo[i] = l;
}

// X [R,C] fp32 -> hi/lo [C,R] fp16   (launch with (32,8) block!)
__global__ __launch_bounds__(256)
void split_tr(const float* __restrict__ x, unsigned short* __restrict__ hi,
              unsigned short* __restrict__ lo, int R, int C)
{
    __shared__ float t[32][33];
    const int c0 = blockIdx.x * 32, r0 = blockIdx.y * 32;
    const int tx = threadIdx.x, ty = threadIdx.y;
#pragma unroll
    for (int j = 0; j < 32; j += 8)
        t[ty + j][tx] = x[(size_t)(r0 + ty + j) * C + c0 + tx];
    __syncthreads();
#pragma unroll
    for (int j = 0; j < 32; j += 8) {
        float v = t[tx][ty + j];
        unsigned short h, l;
        split1(v, h, l);
        size_t o = (size_t)(c0 + ty + j) * R + r0 + tx;
        hi[o] = h; lo[o] = l;
    }
}

// tokens: single read -> direct split [T,E] AND transposed split [E,T]
// (launch with (32,8) block!)
__global__ __launch_bounds__(256)
void split_both(const float* __restrict__ x,
                unsigned short* __restrict__ hiD, unsigned short* __restrict__ loD,
                unsigned short* __restrict__ hiT, unsigned short* __restrict__ loT)
{
    __shared__ float t[32][33];
    const int c0 = blockIdx.x * 32, r0 = blockIdx.y * 32;
    const int tx = threadIdx.x, ty = threadIdx.y;
#pragma unroll
    for (int j = 0; j < 32; j += 8) {
        float v = x[(size_t)(r0 + ty + j) * EE + c0 + tx];
        t[ty + j][tx] = v;
        unsigned short h, l;
        split1(v, h, l);
        size_t o = (size_t)(r0 + ty + j) * EE + c0 + tx;
        hiD[o] = h; loD[o] = l;
    }
    __syncthreads();
#pragma unroll
    for (int j = 0; j < 32; j += 8) {
        float v = t[tx][ty + j];
        unsigned short h, l;
        split1(v, h, l);
        size_t o = (size_t)(c0 + ty + j) * TT + r0 + tx;
        hiT[o] = h; loT[o] = l;
    }
}

// mirror lower triangle of G to upper (32x32 tiles; (32,8) block!)
__global__ __launch_bounds__(256)
void mirror_upper(float* __restrict__ G)
{
    const int txb = blockIdx.x, tyb = blockIdx.y;
    if (txb <= tyb) return;
    __shared__ float t[32][33];
    const int sr = txb * 32, sc = tyb * 32;
    const int tx = threadIdx.x, ty = threadIdx.y;
#pragma unroll
    for (int j = 0; j < 32; j += 8)
        t[ty + j][tx] = G[(size_t)(sr + ty + j) * EE + sc + tx];
    __syncthreads();
#pragma unroll
    for (int j = 0; j < 32; j += 8)
        G[(size_t)(sc + ty + j) * EE + sr + tx] = t[tx][ty + j];
}

__global__ __launch_bounds__(256)
void colsum_kernel(const float* __restrict__ X, float* __restrict__ s)
{
    const int e = blockIdx.x * 256 + threadIdx.x;
    const int t0 = blockIdx.y * (TT / 32);
    float acc = 0.f;
    for (int t = t0; t < t0 + TT / 32; t++) acc += X[(size_t)t * EE + e];
    atomicAdd(&s[e], acc);
}

__global__ __launch_bounds__(256)
void gemv_tn(const float* __restrict__ W, const float* __restrict__ s,
             float* __restrict__ out)
{
    const int m = blockIdx.x * 256 + threadIdx.x;
    const int k0 = blockIdx.y * 256;
    float acc = 0.f;
    for (int k = k0; k < k0 + 256; k++) acc += W[(size_t)k * EE + m] * s[k];
    atomicAdd(&out[m], acc);
}

// softmax rows with rank-1 bias terms; fused: r[row] = att.bv, att hi/lo out.
__global__ __launch_bounds__(256)
void softmax_fused(const float* __restrict__ S,
                   unsigned short* __restrict__ ATH, unsigned short* __restrict__ ATL,
                   const float* __restrict__ u, const float* __restrict__ w,
                   const float* __restrict__ bq, const float* __restrict__ bk,
                   const float* __restrict__ bv, float* __restrict__ r)
{
    __shared__ float buf[EE];
    __shared__ float red[256];
    const int row = blockIdx.x;
    const int tid = threadIdx.x;
    const float* p = S + (size_t)row * EE;
    const float ur = u[row], br = bq[row];

    float lmax = -INFINITY;
    for (int i = tid; i < EE; i += 256) {
        float v = p[i] + ur * bk[i] + br * (w[i] + (float)TT * bk[i]);
        buf[i] = v;
        lmax = fmaxf(lmax, v);
    }
    red[tid] = lmax;
    __syncthreads();
#pragma unroll
    for (int s = 128; s > 0; s >>= 1) {
        if (tid < s) red[tid] = fmaxf(red[tid], red[tid + s]);
        __syncthreads();
    }
    const float m = red[0];
    __syncthreads();
    float lsum = 0.f;
    for (int i = tid; i < EE; i += 256) {
        float e = expf(buf[i] - m);
        buf[i] = e;
        lsum += e;
    }
    red[tid] = lsum;
    __syncthreads();
#pragma unroll
    for (int s = 128; s > 0; s >>= 1) {
        if (tid < s) red[tid] += red[tid + s];
        __syncthreads();
    }
    const float inv = 1.0f / red[0];
    __syncthreads();
    // r[row] = sum(att * bv) = inv * sum(buf * bv)
    float rsum = 0.f;
    for (int i = tid; i < EE; i += 256) rsum += buf[i] * bv[i];
    red[tid] = rsum;
    __syncthreads();
#pragma unroll
    for (int s = 128; s > 0; s >>= 1) {
        if (tid < s) red[tid] += red[tid + s];
        __syncthreads();
    }
    if (tid == 0) r[row] = red[0] * inv;
    // att hi/lo
    for (int i = tid; i < EE; i += 256) {
        unsigned short h, l;
        split1(buf[i] * inv, h, l);
        ATH[(size_t)row * EE + i] = h;
        ATL[(size_t)row * EE + i] = l;
    }
}

// ============================ host side =====================================
extern "C" void kernel_launch(void* const* d_in, const int* in_sizes, int n_in,
                              void* d_out, int out_size)
{
    const float* tokens = (const float*)d_in[0];
    const float* Wq = (const float*)d_in[1];
    const float* bq = (const float*)d_in[2];
    const float* Wk = (const float*)d_in[3];
    const float* bk = (const float*)d_in[4];
    const float* Wv = (const float*)d_in[5];
    const float* bv = (const float*)d_in[6];
    const float* Wp = (const float*)d_in[7];
    const float* bp = (const float*)d_in[8];
    float* out = (float*)d_out;

    unsigned char* base;
    cudaGetSymbolAddress((void**)&base, g_scratch);
#define PF(off) ((float*)(base + (off)))
#define PU(off) ((unsigned short*)(base + (off)))

    cudaFuncSetAttribute(hm_gemm<0,0,true,3>,  cudaFuncAttributeMaxDynamicSharedMemorySize, GemmCfg<3>::SMEM);
    cudaFuncSetAttribute(hm_gemm<0,1,false,3>, cudaFuncAttributeMaxDynamicSharedMemorySize, GemmCfg<3>::SMEM);
    cudaFuncSetAttribute(hm_gemm<0,0,false,3>, cudaFuncAttributeMaxDynamicSharedMemorySize, GemmCfg<3>::SMEM);
    cudaFuncSetAttribute(hm_gemm<2,1,false,1>, cudaFuncAttributeMaxDynamicSharedMemorySize, GemmCfg<1>::SMEM);
    cudaFuncSetAttribute(hm_gemm<1,0,false,1>, cudaFuncAttributeMaxDynamicSharedMemorySize, GemmCfg<1>::SMEM);

    const dim3 blk(256), tb(32, 8);
    float* s = PF(OFF_VS); float* u = PF(OFF_VU);
    float* w = PF(OFF_VW); float* r = PF(OFF_VR);

    // 0. zero s,u,w (atomic accumulators)
    cudaMemsetAsync(base + OFF_VS, 0, 49152);

    // 1. s = colsum(X) ; tokens -> tok h/l AND tokT h/l in one pass
    colsum_kernel<<<dim3(EE / 256, 32), blk>>>(tokens, s);
    split_both<<<dim3(EE / 32, TT / 32), tb>>>(tokens,
        PU(OFF_TOKH), PU(OFF_TOKL), PU(OFF_TOKTH), PU(OFF_TOKTL));

    // 2. G = X^T X (lower triangle, 3-term), mirror, split
    hm_gemm<0,0,true,3><<<dim3(EE/128, EE/128), blk, GemmCfg<3>::SMEM>>>(
        PU(OFF_TOKTH), PU(OFF_TOKTL), PU(OFF_TOKTH), PU(OFF_TOKTL),
        nullptr, nullptr, PF(OFF_GF), nullptr, nullptr, EE, TT);
    mirror_upper<<<dim3(EE/32, EE/32), tb>>>(PF(OFF_GF));
    {
        size_t n4 = (size_t)EE * EE / 4;
        split_dir<<<(unsigned)((n4 + 255) / 256), blk>>>(
            (const float4*)PF(OFF_GF), (ushort4*)PU(OFF_GH), (ushort4*)PU(OFF_GL), n4);
    }

    // 3. P1 = Wq^T G  (3-term, fused split out) ; u = Wq^T s
    split_tr<<<dim3(EE / 32, EE / 32), tb>>>(Wq, PU(OFF_WQTH), PU(OFF_WQTL), EE, EE);
    gemv_tn<<<dim3(EE / 256, EE / 256), blk>>>(Wq, s, u);
    hm_gemm<0,1,false,3><<<dim3(EE/128, EE/128), blk, GemmCfg<3>::SMEM>>>(
        PU(OFF_WQTH), PU(OFF_WQTL), PU(OFF_GH), PU(OFF_GL),
        nullptr, nullptr, nullptr, PU(OFF_P1H), PU(OFF_P1L), EE, EE);

    // 4. S = P1 Wk (3-term) ; w = Wk^T s
    split_tr<<<dim3(EE / 32, EE / 32), tb>>>(Wk, PU(OFF_WKTH), PU(OFF_WKTL), EE, EE);
    gemv_tn<<<dim3(EE / 256, EE / 256), blk>>>(Wk, s, w);
    hm_gemm<0,0,false,3><<<dim3(EE/128, EE/128), blk, GemmCfg<3>::SMEM>>>(
        PU(OFF_P1H), PU(OFF_P1L), PU(OFF_WKTH), PU(OFF_WKTL),
        nullptr, nullptr, PF(OFF_S), nullptr, nullptr, EE, EE);

    // 5. fused softmax: rank-1 bias + r = att.bv + att hi/lo out
    softmax_fused<<<EE, blk>>>(PF(OFF_S), PU(OFF_ATH), PU(OFF_ATL),
                               u, w, bq, bk, bv, r);

    // 6. U = att Wv^T (3-term: att-lo carries subnormal attention weights)
    {
        size_t n4 = (size_t)EE * EE / 4;
        split_dir<<<(unsigned)((n4 + 255) / 256), blk>>>(
            (const float4*)Wv, (ushort4*)PU(OFF_WVH), (ushort4*)PU(OFF_WVL), n4);
    }
    hm_gemm<0,1,false,3><<<dim3(EE/128, EE/128), blk, GemmCfg<3>::SMEM>>>(
        PU(OFF_ATH), PU(OFF_ATL), PU(OFF_WVH), PU(OFF_WVL),
        nullptr, nullptr, nullptr, PU(OFF_UH), PU(OFF_UL), EE, EE);

    // 7. o = U X^T + r 1^T (1-term hh, 3-stage pipe, fused split out)
    hm_gemm<2,1,false,1><<<dim3(TT/128, EE/128), blk, GemmCfg<1>::SMEM>>>(
        PU(OFF_UH), PU(OFF_UL), PU(OFF_TOKH), PU(OFF_TOKL),
        nullptr, r, nullptr, PU(OFF_OH), PU(OFF_OL), TT, EE);

    // 8. out = o Wp + bp (1-term hh, 3-stage pipe)
    split_tr<<<dim3(TT / 32, TT / 32), tb>>>(Wp, PU(OFF_WPTH), PU(OFF_WPTL), TT, TT);
    hm_gemm<1,0,false,1><<<dim3(TT/128, EE/128), blk, GemmCfg<1>::SMEM>>>(
        PU(OFF_OH), PU(OFF_OL), PU(OFF_WPTH), PU(OFF_WPTL),
        bp, nullptr, out, nullptr, nullptr, TT, TT);
#undef PF
#undef PU
}